// round 6
// baseline (speedup 1.0000x reference)
#include <cuda_runtime.h>
#include <cuda_bf16.h>
#include <cstdint>

// MaxUnpooling2D: B=16, H=64, W=64, C=256, SIZE=(2,2) -> out Bx128x128x256.
// mask index for input (b,h,w,c) always lies inside that element's own 2x2
// output window at channel c (per setup_inputs); windows are disjoint across
// (h,w) and channels are independent, so each output cell has exactly one
// candidate writer: its pooled parent. Invert the scatter into an expand:
// each thread owns input float4s and writes the 4 output cells of each
// window, selecting update-or-zero per lane by comparing the mask value
// against each cell's flat index. Fully coalesced loads/stores, every output
// byte written exactly once, no atomics, no zero-init pass.
//
// Traffic: 67MB updates + 67MB mask (read once, streaming) + 268MB output
// (written once, streaming) = 402MB -> pure HBM roofline.

static constexpr int H  = 64;
static constexpr int W  = 64;
static constexpr int C  = 256;
static constexpr int HO = 128;
static constexpr int WO = 128;
static constexpr int C4 = C / 4;                        // 64 float4 per (b,h,w)
static constexpr unsigned OUT_PER_BATCH = HO * WO * C;  // floats per batch

static constexpr int THREADS = 256;
static constexpr int V = 2;                             // float4s per thread

__device__ __forceinline__ void expand_one(unsigned idx,
                                           const int4 m, const float4 u,
                                           float4* __restrict__ out4)
{
    unsigned c4 = idx & (C4 - 1);          // 6 bits
    unsigned w  = (idx >> 6)  & (W - 1);   // 6 bits
    unsigned h  = (idx >> 12) & (H - 1);   // 6 bits
    unsigned b  =  idx >> 18;              // works for any batch count

    int c  = (int)(c4 << 2);
    int y0 = (int)(h << 1);
    int x0 = (int)(w << 1);
    unsigned outBatch = b * OUT_PER_BATCH;   // in floats

    #pragma unroll
    for (int dy = 0; dy < 2; ++dy) {
        // Row base for (y0+dy, x0), channel c: ((y*WO + x0)*C) + c
        int rowBase = ((((y0 + dy) << 7) + x0) << 8) + c;
        #pragma unroll
        for (int dx = 0; dx < 2; ++dx) {
            int base = rowBase + dx * C;    // dx=1 -> +C floats (next column)
            float4 r;
            r.x = (m.x == base    ) ? u.x : 0.0f;
            r.y = (m.y == base + 1) ? u.y : 0.0f;
            r.z = (m.z == base + 2) ? u.z : 0.0f;
            r.w = (m.w == base + 3) ? u.w : 0.0f;
            // Streaming store: output written once, never re-read.
            __stcs(&out4[(outBatch + (unsigned)base) >> 2], r);
        }
    }
}

__global__ __launch_bounds__(THREADS)
void max_unpool_expand_kernel(const float4* __restrict__ updates4,
                              const int4*   __restrict__ mask4,
                              float4*       __restrict__ out4,
                              unsigned n4)
{
    // Two float4s per thread, block-strided so both loads stay coalesced.
    unsigned i0 = blockIdx.x * (THREADS * V) + threadIdx.x;
    unsigned i1 = i0 + THREADS;

    if (i1 < n4) {
        // Common case: both in range. Front-batch all 4 loads (MLP=4).
        // Streaming hints: inputs read exactly once -> evict-first in L2.
        int4   m0 = __ldcs(&mask4[i0]);
        int4   m1 = __ldcs(&mask4[i1]);
        float4 u0 = __ldcs(&updates4[i0]);
        float4 u1 = __ldcs(&updates4[i1]);
        expand_one(i0, m0, u0, out4);
        expand_one(i1, m1, u1, out4);
    } else if (i0 < n4) {
        int4   m0 = __ldcs(&mask4[i0]);
        float4 u0 = __ldcs(&updates4[i0]);
        expand_one(i0, m0, u0, out4);
    }
}

extern "C" void kernel_launch(void* const* d_in, const int* in_sizes, int n_in,
                              void* d_out, int out_size)
{
    const float4* updates4 = (const float4*)d_in[0];  // float32 updates
    const int4*   mask4    = (const int4*)  d_in[1];  // int32 mask
    float4*       out4     = (float4*)d_out;

    unsigned n4   = (unsigned)(in_sizes[0] / 4);            // input float4 count
    unsigned grid = (n4 + THREADS * V - 1) / (THREADS * V); // 8192 @ B=16

    max_unpool_expand_kernel<<<grid, THREADS>>>(updates4, mask4, out4, n4);
}